// round 5
// baseline (speedup 1.0000x reference)
#include <cuda_runtime.h>
#include <cuda_bf16.h>
#include <math.h>

// Problem constants (fixed shapes per reference)
#define B_   32
#define CI_  512
#define H_   50
#define W_   37
#define HW_  1850
#define AMAX 16650
#define MAXG 32

#define OFF_LOC  (B_*18*HW_)            // 1,065,600
#define OFF_LCLS (OFF_LOC + B_*36*HW_)  // 3,196,800
#define LOSS_BLOCKS 256

// Scratch (device globals — no runtime allocation allowed)
__device__ float g_conv1[B_*CI_*HW_];     // 121 MB rpn_conv1
__device__ float g_cls[B_*18*HW_];        // cls_score
__device__ int   g_labels[B_*AMAX];
__device__ int   g_matched[B_*AMAX];
__device__ float g_partial[LOSS_BLOCKS*2];

// ---------------------------------------------------------------------------
// K1: 3x3 conv + bias + ReLU.  Block: one (b, h) row, 128 Cout.
// Thread tile: 2 Cout x 10 W.  Ci chunked by 8.
// ---------------------------------------------------------------------------
__global__ __launch_bounds__(256, 4)
void conv3x3_kernel(const float* __restrict__ feats,
                    const float* __restrict__ W3,
                    const float* __restrict__ b3) {
    const int h  = blockIdx.x;
    const int b  = blockIdx.y;
    const int co_base = blockIdx.z * 128;
    const int t  = threadIdx.x;        // 256
    const int wg = t & 3;              // w group: w = wg*10 .. wg*10+9
    const int cs = t >> 2;             // 0..63 -> co = co_base+cs, co_base+cs+64

    __shared__ float s_in[8 * 3 * 42];     // [ci][dy][iw+1], iw in [-1,40]
    __shared__ float s_w[8 * 128 * 9];     // [ci][co][tap]

    float acc0[10], acc1[10];
#pragma unroll
    for (int u = 0; u < 10; u++) { acc0[u] = 0.f; acc1[u] = 0.f; }

    for (int ci0 = 0; ci0 < CI_; ci0 += 8) {
        __syncthreads();
        // input tile: 8 ci x 3 rows x 42 cols (zero padded)
        for (int e = t; e < 8 * 3 * 42; e += 256) {
            int ci = e / 126, r = e % 126;
            int dy = r / 42, ix = r % 42;
            int ih = h + dy - 1, iw = ix - 1;
            float v = 0.f;
            if (ih >= 0 && ih < H_ && iw >= 0 && iw < W_)
                v = feats[((b * CI_ + ci0 + ci) * H_ + ih) * W_ + iw];
            s_in[e] = v;
        }
        // weights: 8 ci x 128 co x 9 taps
        for (int e = t; e < 8 * 128 * 9; e += 256) {
            int ci = e / 1152, r = e % 1152;
            int co = r / 9,    tap = r % 9;
            s_w[e] = W3[((co_base + co) * CI_ + ci0 + ci) * 9 + tap];
        }
        __syncthreads();

#pragma unroll
        for (int ci = 0; ci < 8; ci++) {
#pragma unroll
            for (int dy = 0; dy < 3; dy++) {
                float r[12];
                const float* ip = &s_in[(ci * 3 + dy) * 42 + wg * 10];
#pragma unroll
                for (int u = 0; u < 12; u++) r[u] = ip[u];
                const float* wp  = &s_w[(ci * 128 + cs) * 9 + dy * 3];
                const float* wp2 = wp + 64 * 9;
#pragma unroll
                for (int dx = 0; dx < 3; dx++) {
                    float w0 = wp[dx], w1 = wp2[dx];
#pragma unroll
                    for (int u = 0; u < 10; u++) {
                        acc0[u] = fmaf(r[u + dx], w0, acc0[u]);
                        acc1[u] = fmaf(r[u + dx], w1, acc1[u]);
                    }
                }
            }
        }
    }

    const int co0 = co_base + cs, co1 = co0 + 64;
    const float bb0 = b3[co0], bb1 = b3[co1];
#pragma unroll
    for (int u = 0; u < 10; u++) {
        int w = wg * 10 + u;
        if (w < W_) {
            g_conv1[((b * CI_ + co0) * H_ + h) * W_ + w] = fmaxf(acc0[u] + bb0, 0.f);
            g_conv1[((b * CI_ + co1) * H_ + h) * W_ + w] = fmaxf(acc1[u] + bb1, 0.f);
        }
    }
}

// ---------------------------------------------------------------------------
// K2: fused 1x1 convs (18 cls + 36 loc = 54 out ch). Block: one (b, h) row.
// ---------------------------------------------------------------------------
__global__ __launch_bounds__(256, 4)
void conv1x1_kernel(const float* __restrict__ Wcls, const float* __restrict__ bcls,
                    const float* __restrict__ Wloc, const float* __restrict__ bloc,
                    float* __restrict__ out) {
    const int h = blockIdx.x;
    const int b = blockIdx.y;
    const int t = threadIdx.x;        // 256
    const int w  = t % 37;
    const int cq = t / 37;            // cq<6 active (handles 9 co each)

    __shared__ float s_x[32 * 37];
    __shared__ float s_w[32 * 54];

    float acc[9];
#pragma unroll
    for (int j = 0; j < 9; j++) acc[j] = 0.f;

    for (int ci0 = 0; ci0 < CI_; ci0 += 32) {
        __syncthreads();
        for (int e = t; e < 32 * 37; e += 256) {
            int ci = e / 37, ww = e % 37;
            s_x[e] = g_conv1[((b * CI_ + ci0 + ci) * H_ + h) * W_ + ww];
        }
        for (int e = t; e < 32 * 54; e += 256) {
            int ci = e / 54, co = e % 54;
            s_w[e] = (co < 18) ? Wcls[co * CI_ + ci0 + ci]
                               : Wloc[(co - 18) * CI_ + ci0 + ci];
        }
        __syncthreads();
        if (cq < 6) {
#pragma unroll 8
            for (int ci = 0; ci < 32; ci++) {
                float xv = s_x[ci * 37 + w];
#pragma unroll
                for (int j = 0; j < 9; j++)
                    acc[j] = fmaf(xv, s_w[ci * 54 + cq * 9 + j], acc[j]);
            }
        }
    }
    if (cq < 6) {
#pragma unroll
        for (int j = 0; j < 9; j++) {
            int co = cq * 9 + j;
            if (co < 18) {
                float v = acc[j] + bcls[co];
                g_cls[(b * 18 + co) * HW_ + h * W_ + w] = v;
            } else {
                float v = acc[j] + bloc[co - 18];
                out[OFF_LOC + (b * 36 + (co - 18)) * HW_ + h * W_ + w] = v;
            }
        }
    }
}

// ---------------------------------------------------------------------------
// K3: paired softmax  (channel c pairs with c+9)
// ---------------------------------------------------------------------------
__global__ void softmax_kernel(float* __restrict__ out) {
    int idx = blockIdx.x * blockDim.x + threadIdx.x;
    if (idx >= B_ * 9 * HW_) return;
    int p = idx % HW_;
    int r = idx / HW_;
    int c = r % 9, b = r / 9;
    float a0 = g_cls[(b * 18 + c) * HW_ + p];
    float a1 = g_cls[(b * 18 + c + 9) * HW_ + p];
    float m = fmaxf(a0, a1);
    float e0 = expf(a0 - m), e1 = expf(a1 - m);
    float inv = 1.f / (e0 + e1);
    out[(b * 18 + c) * HW_ + p]     = e0 * inv;
    out[(b * 18 + c + 9) * HW_ + p] = e1 * inv;
}

// ---------------------------------------------------------------------------
// K4: IoU matching. One block per batch element. Labels + matched gt index.
// Replicates jnp.argmax first-index tie-breaking.
// ---------------------------------------------------------------------------
__global__ __launch_bounds__(256)
void match_kernel(const float* __restrict__ anchors, const float* __restrict__ gt,
                  int A, int G) {
    const int b = blockIdx.x;
    const int t = threadIdx.x;

    __shared__ float s_gt[MAXG * 4];
    __shared__ float s_ag[MAXG];
    if (t < G * 4) s_gt[t] = gt[b * G * 4 + t];
    __syncthreads();
    if (t < G) s_ag[t] = (s_gt[t*4+2] - s_gt[t*4]) * (s_gt[t*4+3] - s_gt[t*4+1]);
    __syncthreads();

    float bi[MAXG]; int bidx[MAXG];
    for (int g = 0; g < G; g++) { bi[g] = -1.f; bidx[g] = 0x7fffffff; }

    for (int s = t; s < A; s += 256) {
        float ax1 = anchors[s*4], ay1 = anchors[s*4+1];
        float ax2 = anchors[s*4+2], ay2 = anchors[s*4+3];
        float aa = (ax2 - ax1) * (ay2 - ay1);
        float mx = -1.f; int mg = 0;
        for (int g = 0; g < G; g++) {
            float ix1 = fmaxf(ax1, s_gt[g*4]);
            float iy1 = fmaxf(ay1, s_gt[g*4+1]);
            float ix2 = fminf(ax2, s_gt[g*4+2]);
            float iy2 = fminf(ay2, s_gt[g*4+3]);
            float iw = ix2 - ix1; if (iw < 0.f) iw = 0.f;
            float ih = iy2 - iy1; if (ih < 0.f) ih = 0.f;
            float inter = iw * ih;
            float iou = inter / fmaxf(aa + s_ag[g] - inter, 1e-8f);
            if (iou > mx) { mx = iou; mg = g; }              // first-max per anchor
            if (iou > bi[g] || (iou == bi[g] && s < bidx[g])) { bi[g] = iou; bidx[g] = s; }
        }
        g_labels[b * AMAX + s]  = (mx > 0.7f) ? 1 : 0;
        g_matched[b * AMAX + s] = mg;
    }

    // reduce best anchor per gt (lowest index wins on ties)
    __shared__ float r_bi[8 * MAXG];
    __shared__ int   r_bidx[8 * MAXG];
    int lane = t & 31, wid = t >> 5;
    for (int g = 0; g < G; g++) {
        float v = bi[g]; int id = bidx[g];
        for (int off = 16; off; off >>= 1) {
            float ov = __shfl_down_sync(0xffffffff, v, off);
            int  oid = __shfl_down_sync(0xffffffff, id, off);
            if (ov > v || (ov == v && oid < id)) { v = ov; id = oid; }
        }
        if (lane == 0) { r_bi[wid * MAXG + g] = v; r_bidx[wid * MAXG + g] = id; }
    }
    __syncthreads();
    if (t < G) {
        float v = r_bi[t]; int id = r_bidx[t];
        for (int w2 = 1; w2 < 8; w2++) {
            float ov = r_bi[w2 * MAXG + t]; int oid = r_bidx[w2 * MAXG + t];
            if (ov > v || (ov == v && oid < id)) { v = ov; id = oid; }
        }
        if (id < A) g_labels[b * AMAX + id] = 1;
    }
}

// ---------------------------------------------------------------------------
// K5: losses (deterministic block partial sums)
// ---------------------------------------------------------------------------
__global__ __launch_bounds__(256)
void loss_kernel(const float* __restrict__ gt, const int* __restrict__ idxs,
                 const float* __restrict__ out, int A, int G) {
    float lc = 0.f, ll = 0.f;
    for (int idx = blockIdx.x * blockDim.x + threadIdx.x; idx < B_ * A;
         idx += gridDim.x * blockDim.x) {
        int b = idx / A, s = idx % A;
        int i = idxs[s];
        // logits_sel mapping: i = c*1850 + h*37 + w  (pair channels c, c+9)
        int c = i / HW_, p = i % HW_;
        float x0 = g_cls[(b * 18 + c) * HW_ + p];
        float x1 = g_cls[(b * 18 + c + 9) * HW_ + p];
        int lab = g_labels[b * AMAX + s];
        float m = fmaxf(x0, x1);
        float lse = m + logf(expf(x0 - m) + expf(x1 - m));
        lc += lse - (lab ? x1 : x0);
        if (lab) {
            int mg = g_matched[b * AMAX + s];
            // loc_sel mapping: i = (h*37 + w)*9 + k,  channel = 4k+d
            int hh = i / 333, r2 = i % 333;
            int ww = r2 / 9,  k = r2 % 9;
#pragma unroll
            for (int d = 0; d < 4; d++) {
                float lv = out[OFF_LOC + (b * 36 + k * 4 + d) * HW_ + hh * W_ + ww];
                float tv = gt[(b * G + mg) * 4 + d];
                float dd = lv - tv, ad = fabsf(dd);
                ll += (ad < 1.f) ? 0.5f * dd * dd : ad - 0.5f;
            }
        }
    }
    __shared__ float sc[256], sl[256];
    sc[threadIdx.x] = lc; sl[threadIdx.x] = ll;
    __syncthreads();
    for (int o = 128; o; o >>= 1) {
        if (threadIdx.x < o) {
            sc[threadIdx.x] += sc[threadIdx.x + o];
            sl[threadIdx.x] += sl[threadIdx.x + o];
        }
        __syncthreads();
    }
    if (threadIdx.x == 0) {
        g_partial[blockIdx.x * 2]     = sc[0];
        g_partial[blockIdx.x * 2 + 1] = sl[0];
    }
}

__global__ void finalize_kernel(int A, float* __restrict__ out) {
    __shared__ float sc[256], sl[256];
    float c = 0.f, l = 0.f;
    for (int i = threadIdx.x; i < LOSS_BLOCKS; i += 256) {
        c += g_partial[i * 2];
        l += g_partial[i * 2 + 1];
    }
    sc[threadIdx.x] = c; sl[threadIdx.x] = l;
    __syncthreads();
    for (int o = 128; o; o >>= 1) {
        if (threadIdx.x < o) {
            sc[threadIdx.x] += sc[threadIdx.x + o];
            sl[threadIdx.x] += sl[threadIdx.x + o];
        }
        __syncthreads();
    }
    if (threadIdx.x == 0) {
        out[OFF_LCLS]     = sc[0] / (float)(B_ * A);
        out[OFF_LCLS + 1] = sl[0] / 256.f;
    }
}

// ---------------------------------------------------------------------------
extern "C" void kernel_launch(void* const* d_in, const int* in_sizes, int n_in,
                              void* d_out, int out_size) {
    const float* feats   = (const float*)d_in[0];
    const float* gt      = (const float*)d_in[1];
    const float* anchors = (const float*)d_in[2];
    const float* W3      = (const float*)d_in[3];
    const float* b3      = (const float*)d_in[4];
    const float* Wcls    = (const float*)d_in[5];
    const float* bcls    = (const float*)d_in[6];
    const float* Wloc    = (const float*)d_in[7];
    const float* bloc    = (const float*)d_in[8];
    const int*   idxs    = (const int*)d_in[9];
    float* out = (float*)d_out;

    const int A = in_sizes[9];                 // kept anchors
    const int G = in_sizes[1] / (B_ * 4);      // gt boxes per image (20)

    conv3x3_kernel<<<dim3(H_, B_, 4), 256>>>(feats, W3, b3);
    conv1x1_kernel<<<dim3(H_, B_), 256>>>(Wcls, bcls, Wloc, bloc, out);
    softmax_kernel<<<(B_ * 9 * HW_ + 255) / 256, 256>>>(out);
    match_kernel<<<B_, 256>>>(anchors, gt, A, G);
    loss_kernel<<<LOSS_BLOCKS, 256>>>(gt, idxs, out, A, G);
    finalize_kernel<<<1, 256>>>(A, out);
}

// round 6
// speedup vs baseline: 1.0706x; 1.0706x over previous
#include <cuda_runtime.h>
#include <cuda_bf16.h>
#include <math.h>

// Problem constants (fixed shapes per reference)
#define B_   32
#define CI_  512
#define H_   50
#define W_   37
#define HW_  1850
#define AMAX 16650
#define MAXG 32

#define OFF_LOC  (B_*18*HW_)            // 1,065,600
#define OFF_LCLS (OFF_LOC + B_*36*HW_)  // 3,196,800
#define LOSS_BLOCKS 256

// Scratch (device globals — no runtime allocation allowed)
__device__ float g_conv1[B_*CI_*HW_];     // 121 MB rpn_conv1
__device__ float g_cls[B_*18*HW_];        // cls_score
__device__ int   g_labels[B_*AMAX];
__device__ int   g_matched[B_*AMAX];
__device__ float g_partial[LOSS_BLOCKS*2];

// packed f32x2 FMA (SASS FFMA2) — ptxas never emits this from C++; PTX only.
__device__ __forceinline__ void ffma2(unsigned long long& d,
                                      unsigned long long a,
                                      unsigned long long b) {
    asm("fma.rn.f32x2 %0, %1, %2, %0;" : "+l"(d) : "l"(a), "l"(b));
}

// ---------------------------------------------------------------------------
// K1: 3x3 conv + bias + ReLU.  Block: one (b, h) row, 128 Cout.
// Thread tile: 2 Cout x 10 W via packed f32x2 FMA.  Ci chunked by 8.
// s_in duplicated (v,v) so the a-operand pair is one LDS.64.
// s_w interleaved (w[cs], w[cs+64]) so the b-operand pair is one LDS.64.
// ---------------------------------------------------------------------------
__global__ __launch_bounds__(256)
void conv3x3_kernel(const float* __restrict__ feats,
                    const float* __restrict__ W3,
                    const float* __restrict__ b3) {
    const int h  = blockIdx.x;
    const int b  = blockIdx.y;
    const int co_base = blockIdx.z * 128;
    const int t  = threadIdx.x;        // 256
    const int wg = t & 3;              // w group: w = wg*10 .. wg*10+9
    const int cs = t >> 2;             // 0..63 -> co = co_base+cs, co_base+cs+64

    __shared__ float2 s_in[8 * 3 * 42];    // [ci][dy][iw+1], value duplicated
    __shared__ float2 s_w[8 * 64 * 9];     // [ci][cs][tap] -> (w_cs, w_cs+64)

    unsigned long long accp[10];
#pragma unroll
    for (int u = 0; u < 10; u++) accp[u] = 0ull;

    for (int ci0 = 0; ci0 < CI_; ci0 += 8) {
        __syncthreads();
        // input tile: 8 ci x 3 rows x 42 cols (zero padded), duplicated lanes
        for (int e = t; e < 8 * 3 * 42; e += 256) {
            int ci = e / 126, r = e % 126;
            int dy = r / 42, ix = r % 42;
            int ih = h + dy - 1, iw = ix - 1;
            float v = 0.f;
            if (ih >= 0 && ih < H_ && iw >= 0 && iw < W_)
                v = feats[((b * CI_ + ci0 + ci) * H_ + ih) * W_ + iw];
            s_in[e] = make_float2(v, v);
        }
        // weights: 8 ci x 64 cs x 9 taps, pair (cs, cs+64)
        for (int e = t; e < 8 * 64 * 9; e += 256) {
            int ci = e / 576, r = e % 576;
            int c2 = r / 9,   tap = r % 9;
            float w0 = W3[((co_base + c2) * CI_ + ci0 + ci) * 9 + tap];
            float w1 = W3[((co_base + c2 + 64) * CI_ + ci0 + ci) * 9 + tap];
            s_w[e] = make_float2(w0, w1);
        }
        __syncthreads();

#pragma unroll
        for (int ci = 0; ci < 8; ci++) {
#pragma unroll
            for (int dy = 0; dy < 3; dy++) {
                unsigned long long r2[12];
                const float2* ip = &s_in[(ci * 3 + dy) * 42 + wg * 10];
#pragma unroll
                for (int u = 0; u < 12; u++)
                    r2[u] = *reinterpret_cast<const unsigned long long*>(&ip[u]);
                const float2* wp = &s_w[(ci * 64 + cs) * 9 + dy * 3];
#pragma unroll
                for (int dx = 0; dx < 3; dx++) {
                    unsigned long long wpair =
                        *reinterpret_cast<const unsigned long long*>(&wp[dx]);
#pragma unroll
                    for (int u = 0; u < 10; u++)
                        ffma2(accp[u], r2[u + dx], wpair);
                }
            }
        }
    }

    const int co0 = co_base + cs, co1 = co0 + 64;
    const float bb0 = b3[co0], bb1 = b3[co1];
#pragma unroll
    for (int u = 0; u < 10; u++) {
        int w = wg * 10 + u;
        if (w < W_) {
            float2 av = *reinterpret_cast<float2*>(&accp[u]);
            g_conv1[((b * CI_ + co0) * H_ + h) * W_ + w] = fmaxf(av.x + bb0, 0.f);
            g_conv1[((b * CI_ + co1) * H_ + h) * W_ + w] = fmaxf(av.y + bb1, 0.f);
        }
    }
}

// ---------------------------------------------------------------------------
// K2: fused 1x1 convs (18 cls + 36 loc = 54 out ch). Block: one (b, h) row.
// ---------------------------------------------------------------------------
__global__ __launch_bounds__(256, 4)
void conv1x1_kernel(const float* __restrict__ Wcls, const float* __restrict__ bcls,
                    const float* __restrict__ Wloc, const float* __restrict__ bloc,
                    float* __restrict__ out) {
    const int h = blockIdx.x;
    const int b = blockIdx.y;
    const int t = threadIdx.x;        // 256
    const int w  = t % 37;
    const int cq = t / 37;            // cq<6 active (handles 9 co each)

    __shared__ float s_x[32 * 37];
    __shared__ float s_w[32 * 54];

    float acc[9];
#pragma unroll
    for (int j = 0; j < 9; j++) acc[j] = 0.f;

    for (int ci0 = 0; ci0 < CI_; ci0 += 32) {
        __syncthreads();
        for (int e = t; e < 32 * 37; e += 256) {
            int ci = e / 37, ww = e % 37;
            s_x[e] = g_conv1[((b * CI_ + ci0 + ci) * H_ + h) * W_ + ww];
        }
        for (int e = t; e < 32 * 54; e += 256) {
            int ci = e / 54, co = e % 54;
            s_w[e] = (co < 18) ? Wcls[co * CI_ + ci0 + ci]
                               : Wloc[(co - 18) * CI_ + ci0 + ci];
        }
        __syncthreads();
        if (cq < 6) {
#pragma unroll 8
            for (int ci = 0; ci < 32; ci++) {
                float xv = s_x[ci * 37 + w];
#pragma unroll
                for (int j = 0; j < 9; j++)
                    acc[j] = fmaf(xv, s_w[ci * 54 + cq * 9 + j], acc[j]);
            }
        }
    }
    if (cq < 6) {
#pragma unroll
        for (int j = 0; j < 9; j++) {
            int co = cq * 9 + j;
            if (co < 18) {
                float v = acc[j] + bcls[co];
                g_cls[(b * 18 + co) * HW_ + h * W_ + w] = v;
            } else {
                float v = acc[j] + bloc[co - 18];
                out[OFF_LOC + (b * 36 + (co - 18)) * HW_ + h * W_ + w] = v;
            }
        }
    }
}

// ---------------------------------------------------------------------------
// K3: paired softmax  (channel c pairs with c+9)
// ---------------------------------------------------------------------------
__global__ void softmax_kernel(float* __restrict__ out) {
    int idx = blockIdx.x * blockDim.x + threadIdx.x;
    if (idx >= B_ * 9 * HW_) return;
    int p = idx % HW_;
    int r = idx / HW_;
    int c = r % 9, b = r / 9;
    float a0 = g_cls[(b * 18 + c) * HW_ + p];
    float a1 = g_cls[(b * 18 + c + 9) * HW_ + p];
    float m = fmaxf(a0, a1);
    float e0 = expf(a0 - m), e1 = expf(a1 - m);
    float inv = 1.f / (e0 + e1);
    out[(b * 18 + c) * HW_ + p]     = e0 * inv;
    out[(b * 18 + c + 9) * HW_ + p] = e1 * inv;
}

// ---------------------------------------------------------------------------
// K4: IoU matching. One block per batch element. Labels + matched gt index.
// Replicates jnp.argmax first-index tie-breaking.
// ---------------------------------------------------------------------------
__global__ __launch_bounds__(256)
void match_kernel(const float* __restrict__ anchors, const float* __restrict__ gt,
                  int A, int G) {
    const int b = blockIdx.x;
    const int t = threadIdx.x;

    __shared__ float s_gt[MAXG * 4];
    __shared__ float s_ag[MAXG];
    if (t < G * 4) s_gt[t] = gt[b * G * 4 + t];
    __syncthreads();
    if (t < G) s_ag[t] = (s_gt[t*4+2] - s_gt[t*4]) * (s_gt[t*4+3] - s_gt[t*4+1]);
    __syncthreads();

    float bi[MAXG]; int bidx[MAXG];
    for (int g = 0; g < G; g++) { bi[g] = -1.f; bidx[g] = 0x7fffffff; }

    for (int s = t; s < A; s += 256) {
        float ax1 = anchors[s*4], ay1 = anchors[s*4+1];
        float ax2 = anchors[s*4+2], ay2 = anchors[s*4+3];
        float aa = (ax2 - ax1) * (ay2 - ay1);
        float mx = -1.f; int mg = 0;
        for (int g = 0; g < G; g++) {
            float ix1 = fmaxf(ax1, s_gt[g*4]);
            float iy1 = fmaxf(ay1, s_gt[g*4+1]);
            float ix2 = fminf(ax2, s_gt[g*4+2]);
            float iy2 = fminf(ay2, s_gt[g*4+3]);
            float iw = ix2 - ix1; if (iw < 0.f) iw = 0.f;
            float ih = iy2 - iy1; if (ih < 0.f) ih = 0.f;
            float inter = iw * ih;
            float iou = inter / fmaxf(aa + s_ag[g] - inter, 1e-8f);
            if (iou > mx) { mx = iou; mg = g; }              // first-max per anchor
            if (iou > bi[g] || (iou == bi[g] && s < bidx[g])) { bi[g] = iou; bidx[g] = s; }
        }
        g_labels[b * AMAX + s]  = (mx > 0.7f) ? 1 : 0;
        g_matched[b * AMAX + s] = mg;
    }

    // reduce best anchor per gt (lowest index wins on ties)
    __shared__ float r_bi[8 * MAXG];
    __shared__ int   r_bidx[8 * MAXG];
    int lane = t & 31, wid = t >> 5;
    for (int g = 0; g < G; g++) {
        float v = bi[g]; int id = bidx[g];
        for (int off = 16; off; off >>= 1) {
            float ov = __shfl_down_sync(0xffffffff, v, off);
            int  oid = __shfl_down_sync(0xffffffff, id, off);
            if (ov > v || (ov == v && oid < id)) { v = ov; id = oid; }
        }
        if (lane == 0) { r_bi[wid * MAXG + g] = v; r_bidx[wid * MAXG + g] = id; }
    }
    __syncthreads();
    if (t < G) {
        float v = r_bi[t]; int id = r_bidx[t];
        for (int w2 = 1; w2 < 8; w2++) {
            float ov = r_bi[w2 * MAXG + t]; int oid = r_bidx[w2 * MAXG + t];
            if (ov > v || (ov == v && oid < id)) { v = ov; id = oid; }
        }
        if (id < A) g_labels[b * AMAX + id] = 1;
    }
}

// ---------------------------------------------------------------------------
// K5: losses (deterministic block partial sums)
// ---------------------------------------------------------------------------
__global__ __launch_bounds__(256)
void loss_kernel(const float* __restrict__ gt, const int* __restrict__ idxs,
                 const float* __restrict__ out, int A, int G) {
    float lc = 0.f, ll = 0.f;
    for (int idx = blockIdx.x * blockDim.x + threadIdx.x; idx < B_ * A;
         idx += gridDim.x * blockDim.x) {
        int b = idx / A, s = idx % A;
        int i = idxs[s];
        // logits_sel mapping: i = c*1850 + h*37 + w  (pair channels c, c+9)
        int c = i / HW_, p = i % HW_;
        float x0 = g_cls[(b * 18 + c) * HW_ + p];
        float x1 = g_cls[(b * 18 + c + 9) * HW_ + p];
        int lab = g_labels[b * AMAX + s];
        float m = fmaxf(x0, x1);
        float lse = m + logf(expf(x0 - m) + expf(x1 - m));
        lc += lse - (lab ? x1 : x0);
        if (lab) {
            int mg = g_matched[b * AMAX + s];
            // loc_sel mapping: i = (h*37 + w)*9 + k,  channel = 4k+d
            int hh = i / 333, r2 = i % 333;
            int ww = r2 / 9,  k = r2 % 9;
#pragma unroll
            for (int d = 0; d < 4; d++) {
                float lv = out[OFF_LOC + (b * 36 + k * 4 + d) * HW_ + hh * W_ + ww];
                float tv = gt[(b * G + mg) * 4 + d];
                float dd = lv - tv, ad = fabsf(dd);
                ll += (ad < 1.f) ? 0.5f * dd * dd : ad - 0.5f;
            }
        }
    }
    __shared__ float sc[256], sl[256];
    sc[threadIdx.x] = lc; sl[threadIdx.x] = ll;
    __syncthreads();
    for (int o = 128; o; o >>= 1) {
        if (threadIdx.x < o) {
            sc[threadIdx.x] += sc[threadIdx.x + o];
            sl[threadIdx.x] += sl[threadIdx.x + o];
        }
        __syncthreads();
    }
    if (threadIdx.x == 0) {
        g_partial[blockIdx.x * 2]     = sc[0];
        g_partial[blockIdx.x * 2 + 1] = sl[0];
    }
}

__global__ void finalize_kernel(int A, float* __restrict__ out) {
    __shared__ float sc[256], sl[256];
    float c = 0.f, l = 0.f;
    for (int i = threadIdx.x; i < LOSS_BLOCKS; i += 256) {
        c += g_partial[i * 2];
        l += g_partial[i * 2 + 1];
    }
    sc[threadIdx.x] = c; sl[threadIdx.x] = l;
    __syncthreads();
    for (int o = 128; o; o >>= 1) {
        if (threadIdx.x < o) {
            sc[threadIdx.x] += sc[threadIdx.x + o];
            sl[threadIdx.x] += sl[threadIdx.x + o];
        }
        __syncthreads();
    }
    if (threadIdx.x == 0) {
        out[OFF_LCLS]     = sc[0] / (float)(B_ * A);
        out[OFF_LCLS + 1] = sl[0] / 256.f;
    }
}

// ---------------------------------------------------------------------------
extern "C" void kernel_launch(void* const* d_in, const int* in_sizes, int n_in,
                              void* d_out, int out_size) {
    const float* feats   = (const float*)d_in[0];
    const float* gt      = (const float*)d_in[1];
    const float* anchors = (const float*)d_in[2];
    const float* W3      = (const float*)d_in[3];
    const float* b3      = (const float*)d_in[4];
    const float* Wcls    = (const float*)d_in[5];
    const float* bcls    = (const float*)d_in[6];
    const float* Wloc    = (const float*)d_in[7];
    const float* bloc    = (const float*)d_in[8];
    const int*   idxs    = (const int*)d_in[9];
    float* out = (float*)d_out;

    const int A = in_sizes[9];                 // kept anchors
    const int G = in_sizes[1] / (B_ * 4);      // gt boxes per image (20)

    conv3x3_kernel<<<dim3(H_, B_, 4), 256>>>(feats, W3, b3);
    conv1x1_kernel<<<dim3(H_, B_), 256>>>(Wcls, bcls, Wloc, bloc, out);
    softmax_kernel<<<(B_ * 9 * HW_ + 255) / 256, 256>>>(out);
    match_kernel<<<B_, 256>>>(anchors, gt, A, G);
    loss_kernel<<<LOSS_BLOCKS, 256>>>(gt, idxs, out, A, G);
    finalize_kernel<<<1, 256>>>(A, out);
}

// round 12
// speedup vs baseline: 2.5938x; 2.4226x over previous
#include <cuda_runtime.h>
#include <cuda_bf16.h>
#include <math.h>

// Problem constants (fixed shapes per reference)
#define B_   32
#define CI_  512
#define H_   50
#define W_   37
#define HW_  1850
#define AMAX 16650
#define MAXG 32
#define KTOT 4608            // 9 taps * 512 ci

#define OFF_LOC  (B_*18*HW_)            // 1,065,600
#define OFF_LCLS (OFF_LOC + B_*36*HW_)  // 3,196,800
#define LOSS_BLOCKS 256

// ---------------------------------------------------------------------------
// Device scratch (no runtime allocation allowed)
// ---------------------------------------------------------------------------
__device__ __align__(256) float g_conv1[B_*CI_*HW_];      // 121 MB rpn_conv1
__device__ __align__(256) float g_featsT[B_*HW_*CI_];     // 121 MB feats, n-major, tf32-rounded
__device__ __align__(256) float g_wT_hi[CI_*KTOT];        // weights [co][tap*512+ci], tf32 hi
__device__ __align__(256) float g_wT_lo[CI_*KTOT];        // weights residual, tf32
__device__ float g_cls[B_*18*HW_];
__device__ int   g_labels[B_*AMAX];
__device__ int   g_matched[B_*AMAX];
__device__ float g_partial[LOSS_BLOCKS*2];

// ---------------------------------------------------------------------------
// helpers
// ---------------------------------------------------------------------------
__device__ __forceinline__ unsigned smem_u32(const void* p) {
    unsigned a;
    asm("{ .reg .u64 t; cvta.to.shared.u64 t, %1; cvt.u32.u64 %0, t; }" : "=r"(a) : "l"(p));
    return a;
}
__device__ __forceinline__ float rna_tf32(float x) {
    float y;
    asm("cvt.rna.tf32.f32 %0, %1;" : "=f"(y) : "f"(x));
    return y;
}

#define CP16(dst, src, sz) \
    asm volatile("cp.async.cg.shared.global [%0], [%1], 16, %2;" \
                 :: "r"(dst), "l"(src), "r"(sz) : "memory")
#define CP_COMMIT() asm volatile("cp.async.commit_group;" ::: "memory")
#define CP_WAIT1()  asm volatile("cp.async.wait_group 1;" ::: "memory")

// m16n8k8 tf32 MMA (sm_80+ PTX, arch-neutral -> legacy HMMA on Blackwell)
#define MMA_TF32(c, a, bfr) \
    asm volatile("mma.sync.aligned.m16n8k8.row.col.f32.tf32.tf32.f32 " \
        "{%0,%1,%2,%3}, {%4,%5,%6,%7}, {%8,%9}, {%0,%1,%2,%3};" \
        : "+f"((c)[0]), "+f"((c)[1]), "+f"((c)[2]), "+f"((c)[3]) \
        : "r"((a)[0]), "r"((a)[1]), "r"((a)[2]), "r"((a)[3]), \
          "r"((bfr)[0]), "r"((bfr)[1]))

// ---------------------------------------------------------------------------
// P1: weight prep — split W3 into tf32 hi + tf32(lo), layout [co][tap*512+ci]
// ---------------------------------------------------------------------------
__global__ void wsplit_kernel(const float* __restrict__ W3) {
    int idx = blockIdx.x * blockDim.x + threadIdx.x;
    if (idx >= CI_ * KTOT) return;
    int co = idx / KTOT, r = idx % KTOT;
    int tap = r / CI_, ci = r % CI_;
    float x = W3[(co * CI_ + ci) * 9 + tap];
    float hi = rna_tf32(x);
    g_wT_hi[idx] = hi;
    g_wT_lo[idx] = rna_tf32(x - hi);
}

// ---------------------------------------------------------------------------
// P2: feats transpose to [b][hw][ci] with tf32 rounding
// ---------------------------------------------------------------------------
__global__ __launch_bounds__(256)
void transpose_kernel(const float* __restrict__ feats) {
    __shared__ float tile[32][33];
    const int b = blockIdx.z;
    const int hw0 = blockIdx.x * 32, ci0 = blockIdx.y * 32;
    const int tx = threadIdx.x % 32, ty = threadIdx.x / 32;  // 32 x 8
#pragma unroll
    for (int i = 0; i < 4; i++) {
        int ci = ci0 + ty + i * 8, hw = hw0 + tx;
        tile[ty + i * 8][tx] = (hw < HW_) ? feats[((size_t)(b * CI_ + ci)) * HW_ + hw] : 0.f;
    }
    __syncthreads();
#pragma unroll
    for (int i = 0; i < 4; i++) {
        int hw = hw0 + ty + i * 8, ci = ci0 + tx;
        if (hw < HW_)
            g_featsT[((size_t)b * HW_ + hw) * CI_ + ci] = rna_tf32(tile[tx][ty + i * 8]);
    }
}

// ---------------------------------------------------------------------------
// K1: 3x3 conv as implicit GEMM on warp-level tf32 MMA.
// Grid (15 ntiles, 32 b, 4 cog). CTA: 128co x 128n, K=4608 in 288 chunks of 16.
// Hi/lo weight compensation accumulates into the same fp32 accumulators.
// Stage (30720 B): A[hl][128 rows][20 floats], B[128 rows][20 floats].
// Smem row stride 20 floats: cp.async dsts 16B-aligned AND conflict-free LDS.
// ---------------------------------------------------------------------------
#define STAGE_B   30720
#define STAGE_F   7680
#define CONV_SMEM (2 * STAGE_B)
#define NCHUNK    288

__global__ __launch_bounds__(256)
void conv_mma_kernel(const float* __restrict__ b3) {
    extern __shared__ float smf[];
    const unsigned sb = smem_u32(smf);
    const int ntile = blockIdx.x, b = blockIdx.y, cog = blockIdx.z;
    const int n0 = ntile * 128;
    const int t = threadIdx.x;
    const int lane = t & 31, wid = t >> 5;
    const int g = lane >> 2, tig = lane & 3;
    const int wm = wid & 1, wn = wid >> 1;     // warp tile: 64co x 32n

    // ---- per-thread load geometry ----
    // A: 4 float4 per chunk
    const float* asrc[4];
    unsigned adst[4];
#pragma unroll
    for (int j = 0; j < 4; j++) {
        int i = t + j * 256;
        int hl = i >> 9, rem = i & 511;
        int row = rem >> 2, q = i & 3;
        asrc[j] = (hl ? g_wT_lo : g_wT_hi) + (size_t)(cog * 128 + row) * KTOT + q * 4;
        adst[j] = sb + hl * 10240 + row * 80 + q * 16;
    }
    // B: 2 float4 per chunk; row r = t>>1
    const int br = t >> 1, bq = t & 1;
    const int bn = n0 + br;
    const int hh = bn / 37, ww = bn % 37;
    const unsigned bdst = sb + 20480 + br * 80 + bq * 32;

    float acc[4][4][4];
#pragma unroll
    for (int mt = 0; mt < 4; mt++)
#pragma unroll
        for (int nt = 0; nt < 4; nt++)
#pragma unroll
            for (int e = 0; e < 4; e++) acc[mt][nt][e] = 0.f;

    // ---- issue loads for chunk sc ----
#define ISSUE(sc) do { \
        int _tap = (sc) >> 5, _ci0 = ((sc) & 31) << 4; \
        unsigned _bb = ((sc) & 1) * STAGE_B; \
        int _koff = _tap * CI_ + _ci0; \
        CP16(adst[0] + _bb, asrc[0] + _koff, 16); \
        CP16(adst[1] + _bb, asrc[1] + _koff, 16); \
        CP16(adst[2] + _bb, asrc[2] + _koff, 16); \
        CP16(adst[3] + _bb, asrc[3] + _koff, 16); \
        int _hp = hh + _tap / 3 - 1, _wp = ww + _tap % 3 - 1; \
        bool _v = (bn < HW_) && _hp >= 0 && _hp < H_ && _wp >= 0 && _wp < W_; \
        unsigned _sz = _v ? 16u : 0u; \
        const float* _bs = _v ? (g_featsT + ((size_t)b * HW_ + _hp * 37 + _wp) * CI_ \
                                 + _ci0 + bq * 8) \
                              : g_featsT; \
        CP16(bdst + _bb, _bs, _sz); \
        CP16(bdst + 16 + _bb, _bs + 4, _sz); \
    } while (0)

    ISSUE(0);
    CP_COMMIT();

    for (int s = 0; s < NCHUNK; s++) {
        if (s + 1 < NCHUNK) ISSUE(s + 1);
        CP_COMMIT();
        CP_WAIT1();
        __syncthreads();

        const float* St = smf + (s & 1) * STAGE_F;
        const float* Bs = St + 5120;
#pragma unroll
        for (int k8 = 0; k8 < 2; k8++) {
            const int k0 = k8 * 8;
            unsigned bfr[4][2];
#pragma unroll
            for (int nt = 0; nt < 4; nt++) {
                int nl = wn * 32 + nt * 8 + g;
                bfr[nt][0] = __float_as_uint(Bs[nl * 20 + k0 + tig]);
                bfr[nt][1] = __float_as_uint(Bs[nl * 20 + k0 + tig + 4]);
            }
#pragma unroll
            for (int hl = 0; hl < 2; hl++) {
                const float* As = St + hl * 2560;
                unsigned afr[4][4];
#pragma unroll
                for (int mt = 0; mt < 4; mt++) {
                    int r0 = wm * 64 + mt * 16 + g;
                    afr[mt][0] = __float_as_uint(As[r0 * 20 + k0 + tig]);
                    afr[mt][1] = __float_as_uint(As[(r0 + 8) * 20 + k0 + tig]);
                    afr[mt][2] = __float_as_uint(As[r0 * 20 + k0 + tig + 4]);
                    afr[mt][3] = __float_as_uint(As[(r0 + 8) * 20 + k0 + tig + 4]);
                }
#pragma unroll
                for (int mt = 0; mt < 4; mt++)
#pragma unroll
                    for (int nt = 0; nt < 4; nt++)
                        MMA_TF32(acc[mt][nt], afr[mt], bfr[nt]);
            }
        }
        __syncthreads();
    }

    // ---- epilogue: bias + ReLU + store ----
#pragma unroll
    for (int mt = 0; mt < 4; mt++) {
        const int co = cog * 128 + wm * 64 + mt * 16 + g;
        const float bias0 = b3[co], bias8 = b3[co + 8];
        const size_t row0 = ((size_t)(b * CI_ + co)) * HW_;
        const size_t row8 = ((size_t)(b * CI_ + co + 8)) * HW_;
#pragma unroll
        for (int nt = 0; nt < 4; nt++) {
            const int n = n0 + wn * 32 + nt * 8 + 2 * tig;
            if (n < HW_) {
                float2 v0 = make_float2(fmaxf(acc[mt][nt][0] + bias0, 0.f),
                                        fmaxf(acc[mt][nt][1] + bias0, 0.f));
                float2 v1 = make_float2(fmaxf(acc[mt][nt][2] + bias8, 0.f),
                                        fmaxf(acc[mt][nt][3] + bias8, 0.f));
                *(float2*)&g_conv1[row0 + n] = v0;
                *(float2*)&g_conv1[row8 + n] = v1;
            }
        }
    }
#undef ISSUE
}

// ---------------------------------------------------------------------------
// K2: fused 1x1 convs (18 cls + 36 loc). Block: one (b, h) row.
// ---------------------------------------------------------------------------
__global__ __launch_bounds__(256, 4)
void conv1x1_kernel(const float* __restrict__ Wcls, const float* __restrict__ bcls,
                    const float* __restrict__ Wloc, const float* __restrict__ bloc,
                    float* __restrict__ out) {
    const int h = blockIdx.x;
    const int b = blockIdx.y;
    const int t = threadIdx.x;
    const int w  = t % 37;
    const int cq = t / 37;

    __shared__ float s_x[32 * 37];
    __shared__ float s_w[32 * 54];

    float acc[9];
#pragma unroll
    for (int j = 0; j < 9; j++) acc[j] = 0.f;

    for (int ci0 = 0; ci0 < CI_; ci0 += 32) {
        __syncthreads();
        for (int e = t; e < 32 * 37; e += 256) {
            int ci = e / 37, ww = e % 37;
            s_x[e] = g_conv1[((size_t)(b * CI_ + ci0 + ci)) * HW_ + h * W_ + ww];
        }
        for (int e = t; e < 32 * 54; e += 256) {
            int ci = e / 54, co = e % 54;
            s_w[e] = (co < 18) ? Wcls[co * CI_ + ci0 + ci]
                               : Wloc[(co - 18) * CI_ + ci0 + ci];
        }
        __syncthreads();
        if (cq < 6) {
#pragma unroll 8
            for (int ci = 0; ci < 32; ci++) {
                float xv = s_x[ci * 37 + w];
#pragma unroll
                for (int j = 0; j < 9; j++)
                    acc[j] = fmaf(xv, s_w[ci * 54 + cq * 9 + j], acc[j]);
            }
        }
    }
    if (cq < 6) {
#pragma unroll
        for (int j = 0; j < 9; j++) {
            int co = cq * 9 + j;
            if (co < 18)
                g_cls[(b * 18 + co) * HW_ + h * W_ + w] = acc[j] + bcls[co];
            else
                out[OFF_LOC + (b * 36 + (co - 18)) * HW_ + h * W_ + w] = acc[j] + bloc[co - 18];
        }
    }
}

// ---------------------------------------------------------------------------
// K3: paired softmax
// ---------------------------------------------------------------------------
__global__ void softmax_kernel(float* __restrict__ out) {
    int idx = blockIdx.x * blockDim.x + threadIdx.x;
    if (idx >= B_ * 9 * HW_) return;
    int p = idx % HW_;
    int r = idx / HW_;
    int c = r % 9, b = r / 9;
    float a0 = g_cls[(b * 18 + c) * HW_ + p];
    float a1 = g_cls[(b * 18 + c + 9) * HW_ + p];
    float m = fmaxf(a0, a1);
    float e0 = expf(a0 - m), e1 = expf(a1 - m);
    float inv = 1.f / (e0 + e1);
    out[(b * 18 + c) * HW_ + p]     = e0 * inv;
    out[(b * 18 + c + 9) * HW_ + p] = e1 * inv;
}

// ---------------------------------------------------------------------------
// K4: IoU matching (jnp.argmax first-index tie-breaking)
// ---------------------------------------------------------------------------
__global__ __launch_bounds__(256)
void match_kernel(const float* __restrict__ anchors, const float* __restrict__ gt,
                  int A, int G) {
    const int b = blockIdx.x;
    const int t = threadIdx.x;

    __shared__ float s_gt[MAXG * 4];
    __shared__ float s_ag[MAXG];
    if (t < G * 4) s_gt[t] = gt[b * G * 4 + t];
    __syncthreads();
    if (t < G) s_ag[t] = (s_gt[t*4+2] - s_gt[t*4]) * (s_gt[t*4+3] - s_gt[t*4+1]);
    __syncthreads();

    float bi[MAXG]; int bidx[MAXG];
    for (int g = 0; g < G; g++) { bi[g] = -1.f; bidx[g] = 0x7fffffff; }

    for (int s = t; s < A; s += 256) {
        float ax1 = anchors[s*4], ay1 = anchors[s*4+1];
        float ax2 = anchors[s*4+2], ay2 = anchors[s*4+3];
        float aa = (ax2 - ax1) * (ay2 - ay1);
        float mx = -1.f; int mg = 0;
        for (int g = 0; g < G; g++) {
            float ix1 = fmaxf(ax1, s_gt[g*4]);
            float iy1 = fmaxf(ay1, s_gt[g*4+1]);
            float ix2 = fminf(ax2, s_gt[g*4+2]);
            float iy2 = fminf(ay2, s_gt[g*4+3]);
            float iw = ix2 - ix1; if (iw < 0.f) iw = 0.f;
            float ih = iy2 - iy1; if (ih < 0.f) ih = 0.f;
            float inter = iw * ih;
            float iou = inter / fmaxf(aa + s_ag[g] - inter, 1e-8f);
            if (iou > mx) { mx = iou; mg = g; }
            if (iou > bi[g] || (iou == bi[g] && s < bidx[g])) { bi[g] = iou; bidx[g] = s; }
        }
        g_labels[b * AMAX + s]  = (mx > 0.7f) ? 1 : 0;
        g_matched[b * AMAX + s] = mg;
    }

    __shared__ float r_bi[8 * MAXG];
    __shared__ int   r_bidx[8 * MAXG];
    int lane = t & 31, wid = t >> 5;
    for (int g = 0; g < G; g++) {
        float v = bi[g]; int id = bidx[g];
        for (int off = 16; off; off >>= 1) {
            float ov = __shfl_down_sync(0xffffffff, v, off);
            int  oid = __shfl_down_sync(0xffffffff, id, off);
            if (ov > v || (ov == v && oid < id)) { v = ov; id = oid; }
        }
        if (lane == 0) { r_bi[wid * MAXG + g] = v; r_bidx[wid * MAXG + g] = id; }
    }
    __syncthreads();
    if (t < G) {
        float v = r_bi[t]; int id = r_bidx[t];
        for (int w2 = 1; w2 < 8; w2++) {
            float ov = r_bi[w2 * MAXG + t]; int oid = r_bidx[w2 * MAXG + t];
            if (ov > v || (ov == v && oid < id)) { v = ov; id = oid; }
        }
        if (id < A) g_labels[b * AMAX + id] = 1;
    }
}

// ---------------------------------------------------------------------------
// K5: losses (deterministic block partial sums)
// ---------------------------------------------------------------------------
__global__ __launch_bounds__(256)
void loss_kernel(const float* __restrict__ gt, const int* __restrict__ idxs,
                 const float* __restrict__ out, int A, int G) {
    float lc = 0.f, ll = 0.f;
    for (int idx = blockIdx.x * blockDim.x + threadIdx.x; idx < B_ * A;
         idx += gridDim.x * blockDim.x) {
        int b = idx / A, s = idx % A;
        int i = idxs[s];
        int c = i / HW_, p = i % HW_;
        float x0 = g_cls[(b * 18 + c) * HW_ + p];
        float x1 = g_cls[(b * 18 + c + 9) * HW_ + p];
        int lab = g_labels[b * AMAX + s];
        float m = fmaxf(x0, x1);
        float lse = m + logf(expf(x0 - m) + expf(x1 - m));
        lc += lse - (lab ? x1 : x0);
        if (lab) {
            int mg = g_matched[b * AMAX + s];
            int hh = i / 333, r2 = i % 333;
            int ww = r2 / 9,  k = r2 % 9;
#pragma unroll
            for (int d = 0; d < 4; d++) {
                float lv = out[OFF_LOC + (b * 36 + k * 4 + d) * HW_ + hh * W_ + ww];
                float tv = gt[(b * G + mg) * 4 + d];
                float dd = lv - tv, ad = fabsf(dd);
                ll += (ad < 1.f) ? 0.5f * dd * dd : ad - 0.5f;
            }
        }
    }
    __shared__ float sc[256], sl[256];
    sc[threadIdx.x] = lc; sl[threadIdx.x] = ll;
    __syncthreads();
    for (int o = 128; o; o >>= 1) {
        if (threadIdx.x < o) {
            sc[threadIdx.x] += sc[threadIdx.x + o];
            sl[threadIdx.x] += sl[threadIdx.x + o];
        }
        __syncthreads();
    }
    if (threadIdx.x == 0) {
        g_partial[blockIdx.x * 2]     = sc[0];
        g_partial[blockIdx.x * 2 + 1] = sl[0];
    }
}

__global__ void finalize_kernel(int A, float* __restrict__ out) {
    __shared__ float sc[256], sl[256];
    float c = 0.f, l = 0.f;
    for (int i = threadIdx.x; i < LOSS_BLOCKS; i += 256) {
        c += g_partial[i * 2];
        l += g_partial[i * 2 + 1];
    }
    sc[threadIdx.x] = c; sl[threadIdx.x] = l;
    __syncthreads();
    for (int o = 128; o; o >>= 1) {
        if (threadIdx.x < o) {
            sc[threadIdx.x] += sc[threadIdx.x + o];
            sl[threadIdx.x] += sl[threadIdx.x + o];
        }
        __syncthreads();
    }
    if (threadIdx.x == 0) {
        out[OFF_LCLS]     = sc[0] / (float)(B_ * A);
        out[OFF_LCLS + 1] = sl[0] / 256.f;
    }
}

// ---------------------------------------------------------------------------
extern "C" void kernel_launch(void* const* d_in, const int* in_sizes, int n_in,
                              void* d_out, int out_size) {
    const float* feats   = (const float*)d_in[0];
    const float* gt      = (const float*)d_in[1];
    const float* anchors = (const float*)d_in[2];
    const float* W3      = (const float*)d_in[3];
    const float* b3      = (const float*)d_in[4];
    const float* Wcls    = (const float*)d_in[5];
    const float* bcls    = (const float*)d_in[6];
    const float* Wloc    = (const float*)d_in[7];
    const float* bloc    = (const float*)d_in[8];
    const int*   idxs    = (const int*)d_in[9];
    float* out = (float*)d_out;

    const int A = in_sizes[9];
    const int G = in_sizes[1] / (B_ * 4);

    cudaFuncSetAttribute(conv_mma_kernel,
                         cudaFuncAttributeMaxDynamicSharedMemorySize, CONV_SMEM);

    wsplit_kernel<<<(CI_ * KTOT + 255) / 256, 256>>>(W3);
    transpose_kernel<<<dim3(58, 16, 32), 256>>>(feats);
    conv_mma_kernel<<<dim3(15, 32, 4), 256, CONV_SMEM>>>(b3);
    conv1x1_kernel<<<dim3(H_, B_), 256>>>(Wcls, bcls, Wloc, bloc, out);
    softmax_kernel<<<(B_ * 9 * HW_ + 255) / 256, 256>>>(out);
    match_kernel<<<B_, 256>>>(anchors, gt, A, G);
    loss_kernel<<<LOSS_BLOCKS, 256>>>(gt, idxs, out, A, G);
    finalize_kernel<<<1, 256>>>(A, out);
}

// round 14
// speedup vs baseline: 4.4183x; 1.7034x over previous
#include <cuda_runtime.h>
#include <cuda_bf16.h>
#include <math.h>

// Problem constants (fixed shapes per reference)
#define B_   32
#define CI_  512
#define H_   50
#define W_   37
#define HW_  1850
#define AMAX 16650
#define MAXG 32
#define KTOT 4608            // 9 taps * 512 ci

#define OFF_LOC  (B_*18*HW_)            // 1,065,600
#define OFF_LCLS (OFF_LOC + B_*36*HW_)  // 3,196,800
#define LOSS_BLOCKS 256

// ---------------------------------------------------------------------------
// Device scratch (no runtime allocation allowed)
// ---------------------------------------------------------------------------
__device__ __align__(256) float g_conv1T[B_*HW_*CI_];     // conv1, n-major [b][hw][ci], tf32-rounded
__device__ __align__(256) float g_featsT[B_*HW_*CI_];     // feats, n-major, tf32-rounded
__device__ __align__(256) float g_wT[CI_*KTOT];           // W3 [co][tap*512+ci], tf32
__device__ float g_cls[B_*18*HW_];
__device__ int   g_labels[B_*AMAX];
__device__ int   g_matched[B_*AMAX];
__device__ float g_partial[LOSS_BLOCKS*2];

// ---------------------------------------------------------------------------
// helpers
// ---------------------------------------------------------------------------
__device__ __forceinline__ unsigned smem_u32(const void* p) {
    unsigned a;
    asm("{ .reg .u64 t; cvta.to.shared.u64 t, %1; cvt.u32.u64 %0, t; }" : "=r"(a) : "l"(p));
    return a;
}
__device__ __forceinline__ float rna_tf32(float x) {
    float y;
    asm("cvt.rna.tf32.f32 %0, %1;" : "=f"(y) : "f"(x));
    return y;
}

#define CP16(dst, src, sz) \
    asm volatile("cp.async.cg.shared.global [%0], [%1], 16, %2;" \
                 :: "r"(dst), "l"(src), "r"(sz) : "memory")
#define CP_COMMIT() asm volatile("cp.async.commit_group;" ::: "memory")
#define CP_WAIT1()  asm volatile("cp.async.wait_group 1;" ::: "memory")

// m16n8k8 tf32 MMA (sm_80+ PTX, arch-neutral -> legacy HMMA on Blackwell)
#define MMA_TF32(c, a, bfr) \
    asm volatile("mma.sync.aligned.m16n8k8.row.col.f32.tf32.tf32.f32 " \
        "{%0,%1,%2,%3}, {%4,%5,%6,%7}, {%8,%9}, {%0,%1,%2,%3};" \
        : "+f"((c)[0]), "+f"((c)[1]), "+f"((c)[2]), "+f"((c)[3]) \
        : "r"((a)[0]), "r"((a)[1]), "r"((a)[2]), "r"((a)[3]), \
          "r"((bfr)[0]), "r"((bfr)[1]))

// ---------------------------------------------------------------------------
// P1: weight prep — tf32-round W3, layout [co][tap*512+ci]
// ---------------------------------------------------------------------------
__global__ void wprep_kernel(const float* __restrict__ W3) {
    int idx = blockIdx.x * blockDim.x + threadIdx.x;
    if (idx >= CI_ * KTOT) return;
    int co = idx / KTOT, r = idx % KTOT;
    int tap = r / CI_, ci = r % CI_;
    g_wT[idx] = rna_tf32(W3[(co * CI_ + ci) * 9 + tap]);
}

// ---------------------------------------------------------------------------
// P2: feats transpose to [b][hw][ci] with tf32 rounding
// ---------------------------------------------------------------------------
__global__ __launch_bounds__(256)
void transpose_kernel(const float* __restrict__ feats) {
    __shared__ float tile[32][33];
    const int b = blockIdx.z;
    const int hw0 = blockIdx.x * 32, ci0 = blockIdx.y * 32;
    const int tx = threadIdx.x % 32, ty = threadIdx.x / 32;  // 32 x 8
#pragma unroll
    for (int i = 0; i < 4; i++) {
        int ci = ci0 + ty + i * 8, hw = hw0 + tx;
        tile[ty + i * 8][tx] = (hw < HW_) ? feats[((size_t)(b * CI_ + ci)) * HW_ + hw] : 0.f;
    }
    __syncthreads();
#pragma unroll
    for (int i = 0; i < 4; i++) {
        int hw = hw0 + ty + i * 8, ci = ci0 + tx;
        if (hw < HW_)
            g_featsT[((size_t)b * HW_ + hw) * CI_ + ci] = rna_tf32(tile[tx][ty + i * 8]);
    }
}

// ---------------------------------------------------------------------------
// K1: 3x3 conv as implicit GEMM on warp-level tf32 MMA (uncompensated).
// Grid (15 ntiles, 32 b, 4 cog). CTA: 128co x 128n, K=4608 in 288 chunks of 16.
// Stage (20480 B): A[128 rows][20 floats] @0, B[128 rows][20 floats] @10240.
// Epilogue stores n-major, tf32-rounded (consumed only by 1x1 MMA).
// ---------------------------------------------------------------------------
#define STAGE_B   20480
#define STAGE_F   5120
#define CONV_SMEM (2 * STAGE_B)
#define NCHUNK    288

__global__ __launch_bounds__(256)
void conv_mma_kernel(const float* __restrict__ b3) {
    extern __shared__ float smf[];
    const unsigned sb = smem_u32(smf);
    const int ntile = blockIdx.x, b = blockIdx.y, cog = blockIdx.z;
    const int n0 = ntile * 128;
    const int t = threadIdx.x;
    const int lane = t & 31, wid = t >> 5;
    const int g = lane >> 2, tig = lane & 3;
    const int wm = wid & 1, wn = wid >> 1;     // warp tile: 64co x 32n

    // A: 2 float4 per chunk per thread
    const float* asrc[2];
    unsigned adst[2];
#pragma unroll
    for (int j = 0; j < 2; j++) {
        int i = t + j * 256;
        int row = i >> 2, q = i & 3;
        asrc[j] = g_wT + (size_t)(cog * 128 + row) * KTOT + q * 4;
        adst[j] = sb + row * 80 + q * 16;
    }
    // B: 2 float4 per chunk; row r = t>>1
    const int br = t >> 1, bq = t & 1;
    const int bn = n0 + br;
    const int hh = bn / 37, ww = bn % 37;
    const unsigned bdst = sb + 10240 + br * 80 + bq * 32;

    float acc[4][4][4];
#pragma unroll
    for (int mt = 0; mt < 4; mt++)
#pragma unroll
        for (int nt = 0; nt < 4; nt++)
#pragma unroll
            for (int e = 0; e < 4; e++) acc[mt][nt][e] = 0.f;

#define ISSUE(sc) do { \
        int _tap = (sc) >> 5, _ci0 = ((sc) & 31) << 4; \
        unsigned _bb = ((sc) & 1) * STAGE_B; \
        int _koff = _tap * CI_ + _ci0; \
        CP16(adst[0] + _bb, asrc[0] + _koff, 16); \
        CP16(adst[1] + _bb, asrc[1] + _koff, 16); \
        int _hp = hh + _tap / 3 - 1, _wp = ww + _tap % 3 - 1; \
        bool _v = (bn < HW_) && _hp >= 0 && _hp < H_ && _wp >= 0 && _wp < W_; \
        unsigned _sz = _v ? 16u : 0u; \
        const float* _bs = _v ? (g_featsT + ((size_t)b * HW_ + _hp * 37 + _wp) * CI_ \
                                 + _ci0 + bq * 8) \
                              : g_featsT; \
        CP16(bdst + _bb, _bs, _sz); \
        CP16(bdst + 16 + _bb, _bs + 4, _sz); \
    } while (0)

    ISSUE(0);
    CP_COMMIT();

    for (int s = 0; s < NCHUNK; s++) {
        if (s + 1 < NCHUNK) ISSUE(s + 1);
        CP_COMMIT();
        CP_WAIT1();
        __syncthreads();

        const float* St = smf + (s & 1) * STAGE_F;
        const float* Bs = St + 2560;
#pragma unroll
        for (int k8 = 0; k8 < 2; k8++) {
            const int k0 = k8 * 8;
            unsigned bfr[4][2];
#pragma unroll
            for (int nt = 0; nt < 4; nt++) {
                int nl = wn * 32 + nt * 8 + g;
                bfr[nt][0] = __float_as_uint(Bs[nl * 20 + k0 + tig]);
                bfr[nt][1] = __float_as_uint(Bs[nl * 20 + k0 + tig + 4]);
            }
            unsigned afr[4][4];
#pragma unroll
            for (int mt = 0; mt < 4; mt++) {
                int r0 = wm * 64 + mt * 16 + g;
                afr[mt][0] = __float_as_uint(St[r0 * 20 + k0 + tig]);
                afr[mt][1] = __float_as_uint(St[(r0 + 8) * 20 + k0 + tig]);
                afr[mt][2] = __float_as_uint(St[r0 * 20 + k0 + tig + 4]);
                afr[mt][3] = __float_as_uint(St[(r0 + 8) * 20 + k0 + tig + 4]);
            }
#pragma unroll
            for (int mt = 0; mt < 4; mt++)
#pragma unroll
                for (int nt = 0; nt < 4; nt++)
                    MMA_TF32(acc[mt][nt], afr[mt], bfr[nt]);
        }
        __syncthreads();
    }

    // ---- epilogue: bias + ReLU + tf32-round + n-major store ----
#pragma unroll
    for (int mt = 0; mt < 4; mt++) {
        const int co = cog * 128 + wm * 64 + mt * 16 + g;
        const float bias0 = b3[co], bias8 = b3[co + 8];
#pragma unroll
        for (int nt = 0; nt < 4; nt++) {
            const int n = n0 + wn * 32 + nt * 8 + 2 * tig;
            if (n < HW_) {
                float* p = &g_conv1T[((size_t)b * HW_ + n) * CI_];
                p[co]     = rna_tf32(fmaxf(acc[mt][nt][0] + bias0, 0.f));
                p[co + 8] = rna_tf32(fmaxf(acc[mt][nt][2] + bias8, 0.f));
            }
            if (n + 1 < HW_) {
                float* p = &g_conv1T[((size_t)b * HW_ + n + 1) * CI_];
                p[co]     = rna_tf32(fmaxf(acc[mt][nt][1] + bias0, 0.f));
                p[co + 8] = rna_tf32(fmaxf(acc[mt][nt][3] + bias8, 0.f));
            }
        }
    }
#undef ISSUE
}

// ---------------------------------------------------------------------------
// K2: fused 1x1 convs as tf32 MMA. Grid (15 ntiles, 32 b).
// CTA: 64co(54 real, zero-padded) x 128n, K=512 in 32 chunks of 16.
// Stage (15360 B): A[64][20] @0, B[128][20] @5120.
// ---------------------------------------------------------------------------
#define C1_STAGE_B 15360
#define C1_STAGE_F 3840
#define C1_SMEM    (2 * C1_STAGE_B)

__global__ __launch_bounds__(256)
void conv1x1_mma_kernel(const float* __restrict__ Wcls, const float* __restrict__ bcls,
                        const float* __restrict__ Wloc, const float* __restrict__ bloc,
                        float* __restrict__ out) {
    extern __shared__ float smf[];
    const unsigned sb = smem_u32(smf);
    const int ntile = blockIdx.x, b = blockIdx.y;
    const int n0 = ntile * 128;
    const int t = threadIdx.x;
    const int lane = t & 31, wid = t >> 5;
    const int g = lane >> 2, tig = lane & 3;
    const int wm = wid & 1, wn = wid >> 1;     // warp tile: 32co x 32n

    // A: 1 float4 per chunk per thread (64 rows x 4 quads)
    const int arow = t >> 2, aq = t & 3;
    const float* asrc;
    unsigned asz = 16;
    if (arow < 18)      asrc = Wcls + arow * CI_ + aq * 4;
    else if (arow < 54) asrc = Wloc + (arow - 18) * CI_ + aq * 4;
    else { asrc = Wcls; asz = 0; }
    const unsigned adst = sb + arow * 80 + aq * 16;

    // B: 2 float4 per chunk; row r = t>>1
    const int br = t >> 1, bq = t & 1;
    const int bn = n0 + br;
    const unsigned bsz = (bn < HW_) ? 16u : 0u;
    const float* bsrc = g_conv1T + ((size_t)b * HW_ + (bn < HW_ ? bn : 0)) * CI_ + bq * 8;
    const unsigned bdst = sb + 5120 + br * 80 + bq * 32;

    float acc[2][4][4];
#pragma unroll
    for (int mt = 0; mt < 2; mt++)
#pragma unroll
        for (int nt = 0; nt < 4; nt++)
#pragma unroll
            for (int e = 0; e < 4; e++) acc[mt][nt][e] = 0.f;

#define ISSUE1(sc) do { \
        int _k = (sc) * 16; \
        unsigned _bb = ((sc) & 1) * C1_STAGE_B; \
        CP16(adst + _bb, asrc + _k, asz); \
        CP16(bdst + _bb, bsrc + _k, bsz); \
        CP16(bdst + 16 + _bb, bsrc + _k + 4, bsz); \
    } while (0)

    ISSUE1(0);
    CP_COMMIT();

    for (int s = 0; s < 32; s++) {
        if (s + 1 < 32) ISSUE1(s + 1);
        CP_COMMIT();
        CP_WAIT1();
        __syncthreads();

        const float* St = smf + (s & 1) * C1_STAGE_F;
        const float* Bs = St + 1280;
#pragma unroll
        for (int k8 = 0; k8 < 2; k8++) {
            const int k0 = k8 * 8;
            unsigned bfr[4][2];
#pragma unroll
            for (int nt = 0; nt < 4; nt++) {
                int nl = wn * 32 + nt * 8 + g;
                bfr[nt][0] = __float_as_uint(Bs[nl * 20 + k0 + tig]);
                bfr[nt][1] = __float_as_uint(Bs[nl * 20 + k0 + tig + 4]);
            }
            unsigned afr[2][4];
#pragma unroll
            for (int mt = 0; mt < 2; mt++) {
                int r0 = wm * 32 + mt * 16 + g;
                afr[mt][0] = __float_as_uint(St[r0 * 20 + k0 + tig]);
                afr[mt][1] = __float_as_uint(St[(r0 + 8) * 20 + k0 + tig]);
                afr[mt][2] = __float_as_uint(St[r0 * 20 + k0 + tig + 4]);
                afr[mt][3] = __float_as_uint(St[(r0 + 8) * 20 + k0 + tig + 4]);
            }
#pragma unroll
            for (int mt = 0; mt < 2; mt++)
#pragma unroll
                for (int nt = 0; nt < 4; nt++)
                    MMA_TF32(acc[mt][nt], afr[mt], bfr[nt]);
        }
        __syncthreads();
    }

    // ---- epilogue: route to g_cls (co<18) or loc out (18<=co<54) ----
#pragma unroll
    for (int mt = 0; mt < 2; mt++) {
#pragma unroll
        for (int half = 0; half < 2; half++) {
            const int co = wm * 32 + mt * 16 + g + half * 8;
            if (co >= 54) continue;
            const float bias = (co < 18) ? bcls[co] : bloc[co - 18];
            float* dst = (co < 18) ? &g_cls[(b * 18 + co) * HW_]
                                   : &out[OFF_LOC + (b * 36 + (co - 18)) * HW_];
#pragma unroll
            for (int nt = 0; nt < 4; nt++) {
                const int n = n0 + wn * 32 + nt * 8 + 2 * tig;
                if (n < HW_)     dst[n]     = acc[mt][nt][half * 2]     + bias;
                if (n + 1 < HW_) dst[n + 1] = acc[mt][nt][half * 2 + 1] + bias;
            }
        }
    }
#undef ISSUE1
}

// ---------------------------------------------------------------------------
// K3: paired softmax
// ---------------------------------------------------------------------------
__global__ void softmax_kernel(float* __restrict__ out) {
    int idx = blockIdx.x * blockDim.x + threadIdx.x;
    if (idx >= B_ * 9 * HW_) return;
    int p = idx % HW_;
    int r = idx / HW_;
    int c = r % 9, b = r / 9;
    float a0 = g_cls[(b * 18 + c) * HW_ + p];
    float a1 = g_cls[(b * 18 + c + 9) * HW_ + p];
    float m = fmaxf(a0, a1);
    float e0 = expf(a0 - m), e1 = expf(a1 - m);
    float inv = 1.f / (e0 + e1);
    out[(b * 18 + c) * HW_ + p]     = e0 * inv;
    out[(b * 18 + c + 9) * HW_ + p] = e1 * inv;
}

// ---------------------------------------------------------------------------
// K4: IoU matching — EXACT round-12 kernel (proven bit-compatible labels).
// One block per batch element. Replicates jnp.argmax first-index ties.
// ---------------------------------------------------------------------------
__global__ __launch_bounds__(256)
void match_kernel(const float* __restrict__ anchors, const float* __restrict__ gt,
                  int A, int G) {
    const int b = blockIdx.x;
    const int t = threadIdx.x;

    __shared__ float s_gt[MAXG * 4];
    __shared__ float s_ag[MAXG];
    if (t < G * 4) s_gt[t] = gt[b * G * 4 + t];
    __syncthreads();
    if (t < G) s_ag[t] = (s_gt[t*4+2] - s_gt[t*4]) * (s_gt[t*4+3] - s_gt[t*4+1]);
    __syncthreads();

    float bi[MAXG]; int bidx[MAXG];
    for (int g = 0; g < G; g++) { bi[g] = -1.f; bidx[g] = 0x7fffffff; }

    for (int s = t; s < A; s += 256) {
        float ax1 = anchors[s*4], ay1 = anchors[s*4+1];
        float ax2 = anchors[s*4+2], ay2 = anchors[s*4+3];
        float aa = (ax2 - ax1) * (ay2 - ay1);
        float mx = -1.f; int mg = 0;
        for (int g = 0; g < G; g++) {
            float ix1 = fmaxf(ax1, s_gt[g*4]);
            float iy1 = fmaxf(ay1, s_gt[g*4+1]);
            float ix2 = fminf(ax2, s_gt[g*4+2]);
            float iy2 = fminf(ay2, s_gt[g*4+3]);
            float iw = ix2 - ix1; if (iw < 0.f) iw = 0.f;
            float ih = iy2 - iy1; if (ih < 0.f) ih = 0.f;
            float inter = iw * ih;
            float iou = inter / fmaxf(aa + s_ag[g] - inter, 1e-8f);
            if (iou > mx) { mx = iou; mg = g; }
            if (iou > bi[g] || (iou == bi[g] && s < bidx[g])) { bi[g] = iou; bidx[g] = s; }
        }
        g_labels[b * AMAX + s]  = (mx > 0.7f) ? 1 : 0;
        g_matched[b * AMAX + s] = mg;
    }

    __shared__ float r_bi[8 * MAXG];
    __shared__ int   r_bidx[8 * MAXG];
    int lane = t & 31, wid = t >> 5;
    for (int g = 0; g < G; g++) {
        float v = bi[g]; int id = bidx[g];
        for (int off = 16; off; off >>= 1) {
            float ov = __shfl_down_sync(0xffffffff, v, off);
            int  oid = __shfl_down_sync(0xffffffff, id, off);
            if (ov > v || (ov == v && oid < id)) { v = ov; id = oid; }
        }
        if (lane == 0) { r_bi[wid * MAXG + g] = v; r_bidx[wid * MAXG + g] = id; }
    }
    __syncthreads();
    if (t < G) {
        float v = r_bi[t]; int id = r_bidx[t];
        for (int w2 = 1; w2 < 8; w2++) {
            float ov = r_bi[w2 * MAXG + t]; int oid = r_bidx[w2 * MAXG + t];
            if (ov > v || (ov == v && oid < id)) { v = ov; id = oid; }
        }
        if (id < A) g_labels[b * AMAX + id] = 1;
    }
}

// ---------------------------------------------------------------------------
// K5: losses (deterministic block partial sums)
// ---------------------------------------------------------------------------
__global__ __launch_bounds__(256)
void loss_kernel(const float* __restrict__ gt, const int* __restrict__ idxs,
                 const float* __restrict__ out, int A, int G) {
    float lc = 0.f, ll = 0.f;
    for (int idx = blockIdx.x * blockDim.x + threadIdx.x; idx < B_ * A;
         idx += gridDim.x * blockDim.x) {
        int b = idx / A, s = idx % A;
        int i = idxs[s];
        int c = i / HW_, p = i % HW_;
        float x0 = g_cls[(b * 18 + c) * HW_ + p];
        float x1 = g_cls[(b * 18 + c + 9) * HW_ + p];
        int lab = g_labels[b * AMAX + s];
        float m = fmaxf(x0, x1);
        float lse = m + logf(expf(x0 - m) + expf(x1 - m));
        lc += lse - (lab ? x1 : x0);
        if (lab) {
            int mg = g_matched[b * AMAX + s];
            int hh = i / 333, r2 = i % 333;
            int ww = r2 / 9,  k = r2 % 9;
#pragma unroll
            for (int d = 0; d < 4; d++) {
                float lv = out[OFF_LOC + (b * 36 + k * 4 + d) * HW_ + hh * W_ + ww];
                float tv = gt[(b * G + mg) * 4 + d];
                float dd = lv - tv, ad = fabsf(dd);
                ll += (ad < 1.f) ? 0.5f * dd * dd : ad - 0.5f;
            }
        }
    }
    __shared__ float sc[256], sl[256];
    sc[threadIdx.x] = lc; sl[threadIdx.x] = ll;
    __syncthreads();
    for (int o = 128; o; o >>= 1) {
        if (threadIdx.x < o) {
            sc[threadIdx.x] += sc[threadIdx.x + o];
            sl[threadIdx.x] += sl[threadIdx.x + o];
        }
        __syncthreads();
    }
    if (threadIdx.x == 0) {
        g_partial[blockIdx.x * 2]     = sc[0];
        g_partial[blockIdx.x * 2 + 1] = sl[0];
    }
}

__global__ void finalize_kernel(int A, float* __restrict__ out) {
    __shared__ float sc[256], sl[256];
    float c = 0.f, l = 0.f;
    for (int i = threadIdx.x; i < LOSS_BLOCKS; i += 256) {
        c += g_partial[i * 2];
        l += g_partial[i * 2 + 1];
    }
    sc[threadIdx.x] = c; sl[threadIdx.x] = l;
    __syncthreads();
    for (int o = 128; o; o >>= 1) {
        if (threadIdx.x < o) {
            sc[threadIdx.x] += sc[threadIdx.x + o];
            sl[threadIdx.x] += sl[threadIdx.x + o];
        }
        __syncthreads();
    }
    if (threadIdx.x == 0) {
        out[OFF_LCLS]     = sc[0] / (float)(B_ * A);
        out[OFF_LCLS + 1] = sl[0] / 256.f;
    }
}

// ---------------------------------------------------------------------------
extern "C" void kernel_launch(void* const* d_in, const int* in_sizes, int n_in,
                              void* d_out, int out_size) {
    const float* feats   = (const float*)d_in[0];
    const float* gt      = (const float*)d_in[1];
    const float* anchors = (const float*)d_in[2];
    const float* W3      = (const float*)d_in[3];
    const float* b3      = (const float*)d_in[4];
    const float* Wcls    = (const float*)d_in[5];
    const float* bcls    = (const float*)d_in[6];
    const float* Wloc    = (const float*)d_in[7];
    const float* bloc    = (const float*)d_in[8];
    const int*   idxs    = (const int*)d_in[9];
    float* out = (float*)d_out;

    const int A = in_sizes[9];
    const int G = in_sizes[1] / (B_ * 4);

    cudaFuncSetAttribute(conv_mma_kernel,
                         cudaFuncAttributeMaxDynamicSharedMemorySize, CONV_SMEM);
    cudaFuncSetAttribute(conv1x1_mma_kernel,
                         cudaFuncAttributeMaxDynamicSharedMemorySize, C1_SMEM);

    wprep_kernel<<<(CI_ * KTOT + 255) / 256, 256>>>(W3);
    transpose_kernel<<<dim3(58, 16, 32), 256>>>(feats);
    conv_mma_kernel<<<dim3(15, 32, 4), 256, CONV_SMEM>>>(b3);
    conv1x1_mma_kernel<<<dim3(15, 32), 256, C1_SMEM>>>(Wcls, bcls, Wloc, bloc, out);
    softmax_kernel<<<(B_ * 9 * HW_ + 255) / 256, 256>>>(out);
    match_kernel<<<B_, 256>>>(anchors, gt, A, G);
    loss_kernel<<<LOSS_BLOCKS, 256>>>(gt, idxs, out, A, G);
    finalize_kernel<<<1, 256>>>(A, out);
}